// round 17
// baseline (speedup 1.0000x reference)
#include <cuda_runtime.h>
#include <cuda_bf16.h>

#define TT    2048
#define BB    32
#define DD    512
#define HH    512
#define BTR   (BB * TT)          // 65536
#define NCTA  256
#define NGRP  4                  // batch groups (8 batches each)
#define CPG   64                 // CTAs per group (8 j each)

// ---------------- device scratch ----------------
__device__ float g_proj[(size_t)BTR * DD];               // 128 MB
__device__ float g_pre[(size_t)TT * HH * BB * 4];        // 512 MB  [t][j][b][gate]
__device__ float g_wcat[DD * 4 * HH];                    // 4 MB    [k][c], c = j*4+g
__device__ float g_bcat[4 * HH];
// h exchange per group: plain floats [j512][b8], double-buffered
__device__ __align__(16) float g_hgrp[2][NGRP][HH * 8];  // 128 KB
// one flag per producer CTA, 128B-strided
__device__ unsigned int g_flags[NGRP * CPG * 32];        // 32 KB

// ---------------- helpers ----------------
__device__ __forceinline__ unsigned long long ffma2(unsigned long long a,
                                                    unsigned long long b,
                                                    unsigned long long c) {
    unsigned long long d;
    asm("fma.rn.f32x2 %0, %1, %2, %3;" : "=l"(d) : "l"(a), "l"(b), "l"(c));
    return d;
}
__device__ __forceinline__ unsigned long long addx2(unsigned long long a,
                                                    unsigned long long b) {
    unsigned long long d;
    asm("add.rn.f32x2 %0, %1, %2;" : "=l"(d) : "l"(a), "l"(b));
    return d;
}
__device__ __forceinline__ unsigned long long pack2(float x) {
    unsigned long long d;
    asm("mov.b64 %0, {%1, %1};" : "=l"(d) : "f"(x));
    return d;
}
__device__ __forceinline__ float2 unpack2(unsigned long long v) {
    float2 r;
    asm("mov.b64 {%0, %1}, %2;" : "=f"(r.x), "=f"(r.y) : "l"(v));
    return r;
}
__device__ __forceinline__ float4 ldcv4(const float* p) {
    float4 v;
    asm volatile("ld.global.cv.v4.f32 {%0,%1,%2,%3}, [%4];"
                 : "=f"(v.x), "=f"(v.y), "=f"(v.z), "=f"(v.w) : "l"(p));
    return v;
}
__device__ __forceinline__ unsigned ldacq(const unsigned* p) {
    unsigned v;
    asm volatile("ld.acquire.gpu.u32 %0, [%1];" : "=r"(v) : "l"(p) : "memory");
    return v;
}

__device__ __forceinline__ float sig_(float x) {
    return __fdividef(1.f, 1.f + __expf(-x));
}
__device__ __forceinline__ float tanh_(float x) {
    return 1.f - __fdividef(2.f, __expf(2.f * x) + 1.f);
}

// ---------------- pack weights + init state ----------------
__global__ void pack_kernel(const float* __restrict__ Wf, const float* __restrict__ Wi,
                            const float* __restrict__ Wc, const float* __restrict__ Wo,
                            const float* __restrict__ bf, const float* __restrict__ bi,
                            const float* __restrict__ bc, const float* __restrict__ bo) {
    int idx = blockIdx.x * 256 + threadIdx.x;
    if (idx < DD * 4 * HH) {
        int k = idx >> 11;         // input-half row of W_*
        int c = idx & 2047;        // c = j*4+g
        int j = c >> 2, g = c & 3;
        const float* W = (g == 0) ? Wf : (g == 1) ? Wi : (g == 2) ? Wc : Wo;
        g_wcat[idx] = W[(size_t)k * HH + j];
    }
    if (idx < 4 * HH) {
        int j = idx >> 2, g = idx & 3;
        const float* bv = (g == 0) ? bf : (g == 1) ? bi : (g == 2) ? bc : bo;
        g_bcat[idx] = bv[j];
    }
    if (idx < 2 * NGRP * HH * 8) ((float*)g_hgrp)[idx] = 0.f;   // h0 = 0
    if (idx < NGRP * CPG * 32) g_flags[idx] = 0u;               // gen 0 published
}

// ---------------- fp32 SIMT GEMM, f32x2 accumulation (unchanged, proven) ----------------
__global__ __launch_bounds__(256, 2) void gemm_kernel(
    int stage, const float* __restrict__ Aext, const float* __restrict__ Bext,
    const float* __restrict__ biasext) {
    __shared__ __align__(16) float As[16][132];
    __shared__ __align__(16) float Bs[16][128];

    const float* A    = (stage == 0) ? Aext    : g_proj;
    const float* B    = (stage == 0) ? Bext    : g_wcat;
    const float* bias = (stage == 0) ? biasext : g_bcat;
    float* out = (stage == 0) ? g_proj : g_pre;
    const int ldb = (stage == 0) ? 512 : 2048;

    const int tid = threadIdx.x;
    const int m0 = blockIdx.y * 128;
    const int n0 = blockIdx.x * 128;
    const int tm = tid >> 4, tn = tid & 15;

    unsigned long long acc[4][8];
    #pragma unroll
    for (int p = 0; p < 4; p++)
        #pragma unroll
        for (int n = 0; n < 8; n++) acc[p][n] = 0ull;

    for (int k0 = 0; k0 < 512; k0 += 16) {
        #pragma unroll
        for (int i = 0; i < 2; i++) {
            int idx = tid + i * 256;
            int row = idx >> 2, c4 = idx & 3;
            float4 v = *(const float4*)(A + (size_t)(m0 + row) * 512 + k0 + c4 * 4);
            As[c4 * 4 + 0][row] = v.x;
            As[c4 * 4 + 1][row] = v.y;
            As[c4 * 4 + 2][row] = v.z;
            As[c4 * 4 + 3][row] = v.w;
        }
        #pragma unroll
        for (int i = 0; i < 2; i++) {
            int idx = tid + i * 256;
            int row = idx >> 5, c4 = idx & 31;
            *(float4*)&Bs[row][c4 * 4] =
                *(const float4*)(B + (size_t)(k0 + row) * ldb + n0 + c4 * 4);
        }
        __syncthreads();
        #pragma unroll
        for (int kk = 0; kk < 16; kk++) {
            ulonglong2 aA = *(const ulonglong2*)&As[kk][tm * 8];
            ulonglong2 aB = *(const ulonglong2*)&As[kk][tm * 8 + 4];
            float4 b0 = *(const float4*)&Bs[kk][tn * 8];
            float4 b1 = *(const float4*)&Bs[kk][tn * 8 + 4];
            unsigned long long bd[8];
            bd[0] = pack2(b0.x); bd[1] = pack2(b0.y); bd[2] = pack2(b0.z); bd[3] = pack2(b0.w);
            bd[4] = pack2(b1.x); bd[5] = pack2(b1.y); bd[6] = pack2(b1.z); bd[7] = pack2(b1.w);
            #pragma unroll
            for (int n = 0; n < 8; n++) {
                acc[0][n] = ffma2(aA.x, bd[n], acc[0][n]);
                acc[1][n] = ffma2(aA.y, bd[n], acc[1][n]);
                acc[2][n] = ffma2(aB.x, bd[n], acc[2][n]);
                acc[3][n] = ffma2(aB.y, bd[n], acc[3][n]);
            }
        }
        __syncthreads();
    }

    float4 bs0 = *(const float4*)&bias[n0 + tn * 8];
    float4 bs1 = *(const float4*)&bias[n0 + tn * 8 + 4];
    float bv[8] = {bs0.x, bs0.y, bs0.z, bs0.w, bs1.x, bs1.y, bs1.z, bs1.w};

    #pragma unroll
    for (int p = 0; p < 4; p++) {
        int r0 = m0 + tm * 8 + 2 * p;
        #pragma unroll
        for (int jj = 0; jj < 2; jj++) {
            float2 u0 = unpack2(acc[p][jj * 4 + 0]);
            float2 u1 = unpack2(acc[p][jj * 4 + 1]);
            float2 u2 = unpack2(acc[p][jj * 4 + 2]);
            float2 u3 = unpack2(acc[p][jj * 4 + 3]);
            float4 lo4, hi4;
            lo4.x = u0.x + bv[jj * 4 + 0]; hi4.x = u0.y + bv[jj * 4 + 0];
            lo4.y = u1.x + bv[jj * 4 + 1]; hi4.y = u1.y + bv[jj * 4 + 1];
            lo4.z = u2.x + bv[jj * 4 + 2]; hi4.z = u2.y + bv[jj * 4 + 2];
            lo4.w = u3.x + bv[jj * 4 + 3]; hi4.w = u3.y + bv[jj * 4 + 3];
            if (stage == 0) {
                lo4.x = tanh_(lo4.x); lo4.y = tanh_(lo4.y);
                lo4.z = tanh_(lo4.z); lo4.w = tanh_(lo4.w);
                hi4.x = tanh_(hi4.x); hi4.y = tanh_(hi4.y);
                hi4.z = tanh_(hi4.z); hi4.w = tanh_(hi4.w);
                int c0 = n0 + tn * 8 + jj * 4;
                *(float4*)(out + (size_t)r0 * 512 + c0)       = lo4;
                *(float4*)(out + (size_t)(r0 + 1) * 512 + c0) = hi4;
            } else {
                int b  = r0 >> 11;
                int t0 = r0 & 2047;
                int jglob = ((n0 + tn * 8) >> 2) + jj;
                *(float4*)(out + (((size_t)t0 * 512 + jglob) * 32 + b) * 4)       = lo4;
                *(float4*)(out + (((size_t)(t0 + 1) * 512 + jglob) * 32 + b) * 4) = hi4;
            }
        }
    }
}

// ---------------- persistent scan: 256 CTAs (2/SM), 4 groups x 64 CTAs ----------------
// CTA (grp, cix): batches b0=grp*8..+7, hidden cols j0=cix*8..+7, all 4 gates.
// 256 threads, 8 warps; warp w: k in [w*64,+64).
// Lane = (kq, jl): jl = lane&7, kq = lane>>3; iter i handles k = w*64 + i*4 + kq.
// Weights: 16 uint4 in regs (64 regs). Per iter: 2 LDS.128 h -> 16 FFMA2.
// kq-reduction via shfl_xor(8,16); lanes kq==0 store per-(w,j) partials.
// SMEM per CTA (64KB, weights staged then region reused):
//   stage  [512k][8j] uint4          : 65536 @ 0   (init only)
//   h_s    per-warp [64k][8b] f32    : 16384 @ 0
//   part   [2][8w][8j] 160B-j-stride : 20480 @ 16384
//   c_s    64 f32                    : 256   @ 36864
#define H_OFF     0
#define PART_OFF  16384
#define PART_BUF  10240
#define C_OFF     36864
#define SCAN_SMEM 65536

__global__ __launch_bounds__(256, 2) void lstm_scan_kernel(
    const float* __restrict__ Wf, const float* __restrict__ Wi,
    const float* __restrict__ Wc, const float* __restrict__ Wo,
    float* __restrict__ out) {
    extern __shared__ __align__(16) char smraw[];
    float* c_s = (float*)(smraw + C_OFF);

    const int tid  = threadIdx.x;
    const int lane = tid & 31;
    const int wrp  = tid >> 5;
    const int jl   = lane & 7;
    const int kq   = lane >> 3;
    const int grp  = blockIdx.x >> 6;           // 0..3
    const int cix  = blockIdx.x & 63;           // 0..63
    const int j0   = cix * 8;
    const int b0   = grp * 8;

    // stage weights (rows 512..1023, cols j0..j0+7) into smem, then to regs
    for (int idx = tid; idx < 512 * 8; idx += 256) {
        int k = idx >> 3, j = idx & 7;
        size_t off = (size_t)(512 + k) * HH + (j0 + j);
        uint4 w;
        w.x = __float_as_uint(Wf[off]); w.y = __float_as_uint(Wi[off]);
        w.z = __float_as_uint(Wc[off]); w.w = __float_as_uint(Wo[off]);
        *(uint4*)(smraw + k * 128 + j * 16) = w;
    }
    __syncthreads();
    uint4 wreg[16];
    #pragma unroll
    for (int i = 0; i < 16; i++)
        wreg[i] = *(const uint4*)(smraw + (wrp * 64 + i * 4 + kq) * 128 + jl * 16);
    __syncthreads();   // all reg pulls done before smem region is reused

    if (tid < 64) c_s[tid] = 0.f;

    const char*     hb    = smraw + H_OFF + wrp * 2048 + kq * 32;
    float*          hstg  = (float*)(smraw + H_OFF) + wrp * 512;
    const unsigned* fpoll = g_flags + grp * (CPG * 32) + lane * 32;   // lane, lane+32
    unsigned*       fmine = g_flags + grp * (CPG * 32) + cix * 32;

    for (int t = 0; t < TT; t++) {
        const unsigned tgt = (unsigned)t;
        const int pbuf = t & 1;

        // prefetch this step's input-half pre-activations (epilogue threads)
        float4 pre4 = make_float4(0.f, 0.f, 0.f, 0.f);
        if (tid < 64) {
            int rj = tid >> 3, rb = tid & 7;
            pre4 = *(const float4*)(g_pre + (((size_t)t * 512 + j0 + rj) * 32 + b0 + rb) * 4);
        }

        // ---- wait: 64 producer flags of this group (2 per lane, acquire) ----
        {
            unsigned a = ldacq(fpoll);
            unsigned b = ldacq(fpoll + 32 * 32);
            while (!__all_sync(0xffffffffu, a >= tgt && b >= tgt)) {
                a = ldacq(fpoll);
                b = ldacq(fpoll + 32 * 32);
            }
        }

        // ---- load warp's h slice: contiguous 2KB, .cv (L1 bypass), [k][b] ----
        {
            const float* hg = g_hgrp[t & 1][grp] + wrp * 512;
            #pragma unroll
            for (int i = 0; i < 4; i++) {
                float4 v = ldcv4(hg + (i * 32 + lane) * 4);
                *(float4*)(hstg + (i * 32 + lane) * 4) = v;
            }
        }
        __syncwarp();

        // ---- compute: 16 iters x (2 LDS.128 h + reg weights -> 16 FFMA2) ----
        unsigned long long acc[16];
        #pragma unroll
        for (int q = 0; q < 16; q++) acc[q] = 0ull;
        #pragma unroll
        for (int i = 0; i < 16; i++) {
            ulonglong2 hA = *(const ulonglong2*)(hb + i * 128);
            ulonglong2 hB = *(const ulonglong2*)(hb + i * 128 + 16);
            uint4 w = wreg[i];
            unsigned long long wf = pack2(__uint_as_float(w.x));
            unsigned long long wi = pack2(__uint_as_float(w.y));
            unsigned long long wc = pack2(__uint_as_float(w.z));
            unsigned long long wo = pack2(__uint_as_float(w.w));
            acc[0]  = ffma2(hA.x, wf, acc[0]);  acc[1]  = ffma2(hA.y, wf, acc[1]);
            acc[2]  = ffma2(hB.x, wf, acc[2]);  acc[3]  = ffma2(hB.y, wf, acc[3]);
            acc[4]  = ffma2(hA.x, wi, acc[4]);  acc[5]  = ffma2(hA.y, wi, acc[5]);
            acc[6]  = ffma2(hB.x, wi, acc[6]);  acc[7]  = ffma2(hB.y, wi, acc[7]);
            acc[8]  = ffma2(hA.x, wc, acc[8]);  acc[9]  = ffma2(hA.y, wc, acc[9]);
            acc[10] = ffma2(hB.x, wc, acc[10]); acc[11] = ffma2(hB.y, wc, acc[11]);
            acc[12] = ffma2(hA.x, wo, acc[12]); acc[13] = ffma2(hA.y, wo, acc[13]);
            acc[14] = ffma2(hB.x, wo, acc[14]); acc[15] = ffma2(hB.y, wo, acc[15]);
        }
        // in-register kq reduction: butterfly over lanes 8 and 16 apart
        #pragma unroll
        for (int q = 0; q < 16; q++)
            acc[q] = addx2(acc[q], __shfl_xor_sync(0xffffffffu, acc[q], 8));
        #pragma unroll
        for (int q = 0; q < 16; q++)
            acc[q] = addx2(acc[q], __shfl_xor_sync(0xffffffffu, acc[q], 16));

        if (kq == 0) {   // lanes 0-7 hold warp totals for j = jl
            char* pp = smraw + PART_OFF + pbuf * PART_BUF + wrp * 1280 + jl * 160;
            ulonglong2 v;
            v.x = acc[0];  v.y = acc[1];  *(ulonglong2*)(pp +  0) = v;   // f b0..b3
            v.x = acc[2];  v.y = acc[3];  *(ulonglong2*)(pp + 16) = v;   // f b4..b7
            v.x = acc[4];  v.y = acc[5];  *(ulonglong2*)(pp + 32) = v;   // i
            v.x = acc[6];  v.y = acc[7];  *(ulonglong2*)(pp + 48) = v;
            v.x = acc[8];  v.y = acc[9];  *(ulonglong2*)(pp + 64) = v;   // c
            v.x = acc[10]; v.y = acc[11]; *(ulonglong2*)(pp + 80) = v;
            v.x = acc[12]; v.y = acc[13]; *(ulonglong2*)(pp + 96) = v;   // o
            v.x = acc[14]; v.y = acc[15]; *(ulonglong2*)(pp + 112) = v;
        }

        if (wrp >= 2) {
            // producers: signal partials ready, pipeline into step t+1
            asm volatile("bar.arrive 1, 256;" ::: "memory");
            continue;
        }
        // consumers (warps 0-1): wait for all partials of step t
        asm volatile("bar.sync 1, 256;" ::: "memory");

        {
            int rj = tid >> 3, rb = tid & 7;   // tid < 64
            const char* rp = smraw + PART_OFF + pbuf * PART_BUF + rj * 160 + rb * 4;
            float rf = 0.f, ri = 0.f, rc = 0.f, ro = 0.f;
            #pragma unroll
            for (int w = 0; w < 8; w++) {
                const char* q = rp + w * 1280;
                rf += *(const float*)(q +  0);
                ri += *(const float*)(q + 32);
                rc += *(const float*)(q + 64);
                ro += *(const float*)(q + 96);
            }
            float f  = sig_(pre4.x + rf);
            float ii = sig_(pre4.y + ri);
            float cg = tanh_(pre4.z + rc);
            float o  = sig_(pre4.w + ro);
            float cn = f * c_s[tid] + ii * cg;
            c_s[tid] = cn;
            float h = o * tanh_(cn);
            g_hgrp[(t + 1) & 1][grp][(j0 + rj) * 8 + rb] = h;    // plain store
            out[((size_t)(b0 + rb) * TT + t) * HH + j0 + rj] = h;
        }
        // epilogue-only barrier (cumulative CTA fence), then single release store
        asm volatile("bar.sync 2, 64;" ::: "memory");
        if (tid == 0) {
            asm volatile("st.release.gpu.u32 [%0], %1;"
                         :: "l"(fmine), "r"((unsigned)(t + 1)) : "memory");
        }
    }
}

extern "C" void kernel_launch(void* const* d_in, const int* in_sizes, int n_in,
                              void* d_out, int out_size) {
    const float* X   = (const float*)d_in[0];
    const float* W_p = (const float*)d_in[1];
    const float* b_p = (const float*)d_in[2];
    const float* W_f = (const float*)d_in[3];
    const float* b_f = (const float*)d_in[4];
    const float* W_i = (const float*)d_in[5];
    const float* b_i = (const float*)d_in[6];
    const float* W_c = (const float*)d_in[7];
    const float* b_c = (const float*)d_in[8];
    const float* W_o = (const float*)d_in[9];
    const float* b_o = (const float*)d_in[10];
    float* out = (float*)d_out;

    cudaFuncSetAttribute(lstm_scan_kernel,
                         cudaFuncAttributeMaxDynamicSharedMemorySize, SCAN_SMEM);

    pack_kernel<<<4096, 256>>>(W_f, W_i, W_c, W_o, b_f, b_i, b_c, b_o);
    gemm_kernel<<<dim3(4, 512), 256>>>(0, X, W_p, b_p);
    gemm_kernel<<<dim3(16, 512), 256>>>(1, nullptr, nullptr, nullptr);
    lstm_scan_kernel<<<NCTA, 256, SCAN_SMEM>>>(W_f, W_i, W_c, W_o, out);
}